// round 4
// baseline (speedup 1.0000x reference)
#include <cuda_runtime.h>
#include <cuda_fp16.h>
#include <mma.h>
#include <cstdint>

using namespace nvcuda;

#define NN 100000
#define NE 3200000

// ---------------- static device scratch (no allocations allowed) ----------------
__device__ int     g_deg[NN];
__device__ int     g_off[NN + 1];
__device__ int     g_cursor[NN];
__device__ int2    g_edge[NE];             // (src, bitcast(attn)) sorted by dst
__device__ float   g_hn[(size_t)NN * 128]; // aggregation result (fp32), stride = IN
__device__ __half2 g_xh[(size_t)NN * 64];  // fp16 mirror of x (128 cols)
__device__ __half2 g_hh[(size_t)NN * 64];  // fp16 mirror of current layer output
// fp16 weights (one contiguous pool)
__device__ half g_wpool[2 * (128 * 128 + 128 * 64 + 64 * 32)];

// ---------------- CSR build ----------------
__global__ void k_zero_deg() {
    int i = blockIdx.x * blockDim.x + threadIdx.x;
    if (i < NN) g_deg[i] = 0;
}

__global__ void k_hist(const int* __restrict__ dst) {
    int base = (blockIdx.x * blockDim.x + threadIdx.x) * 4;
    if (base + 3 < NE) {
        int4 d = *(const int4*)&dst[base];
        atomicAdd(&g_deg[d.x], 1);
        atomicAdd(&g_deg[d.y], 1);
        atomicAdd(&g_deg[d.z], 1);
        atomicAdd(&g_deg[d.w], 1);
    } else {
        for (int e = base; e < NE; e++) atomicAdd(&g_deg[dst[e]], 1);
    }
}

// single-block scan: each thread serially owns a contiguous chunk
__global__ void k_scan() {
    __shared__ int part[1024];
    int tid = threadIdx.x;
    const int CH = (NN + 1023) / 1024;
    int beg = tid * CH;
    int end = beg + CH < NN ? beg + CH : NN;
    int s = 0;
    for (int i = beg; i < end; i++) s += g_deg[i];
    part[tid] = s;
    __syncthreads();
    #pragma unroll
    for (int off = 1; off < 1024; off <<= 1) {
        int t = (tid >= off) ? part[tid - off] : 0;
        __syncthreads();
        part[tid] += t;
        __syncthreads();
    }
    int run = tid ? part[tid - 1] : 0;
    for (int i = beg; i < end; i++) {
        int d = g_deg[i];
        g_off[i] = run;
        g_cursor[i] = run;
        run += d;
    }
    if (tid == 1023) g_off[NN] = run;
}

__global__ void k_scatter(const int* __restrict__ src, const int* __restrict__ dst,
                          const float* __restrict__ attn) {
    int base = (blockIdx.x * blockDim.x + threadIdx.x) * 4;
    if (base + 3 < NE) {
        int4   s = *(const int4*)&src[base];
        int4   d = *(const int4*)&dst[base];
        float4 a = *(const float4*)&attn[base];
        int p0 = atomicAdd(&g_cursor[d.x], 1);
        int p1 = atomicAdd(&g_cursor[d.y], 1);
        int p2 = atomicAdd(&g_cursor[d.z], 1);
        int p3 = atomicAdd(&g_cursor[d.w], 1);
        g_edge[p0] = make_int2(s.x, __float_as_int(a.x));
        g_edge[p1] = make_int2(s.y, __float_as_int(a.y));
        g_edge[p2] = make_int2(s.z, __float_as_int(a.z));
        g_edge[p3] = make_int2(s.w, __float_as_int(a.w));
    } else {
        for (int e = base; e < NE; e++) {
            int p = atomicAdd(&g_cursor[dst[e]], 1);
            g_edge[p] = make_int2(src[e], __float_as_int(attn[e]));
        }
    }
}

// ---------------- merged weight fp32 -> fp16 (6 arrays, one kernel) ----------------
__global__ void k_convw_all(const float* __restrict__ W1_0, const float* __restrict__ W2_0,
                            const float* __restrict__ W1_1, const float* __restrict__ W2_1,
                            const float* __restrict__ W1_2, const float* __restrict__ W2_2) {
    const int N0 = 128 * 128, N1 = 128 * 64, N2 = 64 * 32;
    int i = blockIdx.x * blockDim.x + threadIdx.x;
    int total = 2 * (N0 + N1 + N2);
    if (i >= total) return;
    const float* srcs[6] = {W1_0, W2_0, W1_1, W2_1, W1_2, W2_2};
    const int sizes[6] = {N0, N0, N1, N1, N2, N2};
    int rem = i;
    #pragma unroll
    for (int a = 0; a < 6; a++) {
        if (rem < sizes[a]) { g_wpool[i] = __float2half(srcs[a][rem]); return; }
        rem -= sizes[a];
    }
}

// ---------------- copy x into output cols [0,128) + fp16 mirror ----------------
__global__ void k_copy_x(const float* __restrict__ x, float* __restrict__ out) {
    int t = blockIdx.x * blockDim.x + threadIdx.x;
    if (t < NN * 32) {
        int v = t >> 5, c = t & 31;
        float4 val = ((const float4*)(x + (size_t)v * 128))[c];
        ((float4*)(out + (size_t)v * 352))[c] = val;
        g_xh[(size_t)v * 64 + c * 2]     = __floats2half2_rn(val.x, val.y);
        g_xh[(size_t)v * 64 + c * 2 + 1] = __floats2half2_rn(val.z, val.w);
    }
}

// ---------------- aggregation: warp per dst node, CSR gather, edge prefetch ----------------
template <int VEC>
__global__ void k_agg(const __half2* __restrict__ xin) {
    int gw = (blockIdx.x * blockDim.x + threadIdx.x) >> 5;
    if (gw >= NN) return;
    int lane = threadIdx.x & 31;
    int beg = g_off[gw], end = g_off[gw + 1];

    if (VEC == 4) {
        float4 acc = make_float4(0.f, 0.f, 0.f, 0.f);
        int e = beg;
        if (e + 3 < end) {
            int2 c0 = g_edge[e], c1 = g_edge[e + 1], c2 = g_edge[e + 2], c3 = g_edge[e + 3];
            for (;;) {
                int en = e + 4;
                bool more = (en + 3 < end);
                int2 n0, n1, n2, n3;
                if (more) { n0 = g_edge[en]; n1 = g_edge[en + 1]; n2 = g_edge[en + 2]; n3 = g_edge[en + 3]; }
                float2 raw0 = ((const float2*)(xin + (size_t)c0.x * 64))[lane];
                float2 raw1 = ((const float2*)(xin + (size_t)c1.x * 64))[lane];
                float2 raw2 = ((const float2*)(xin + (size_t)c2.x * 64))[lane];
                float2 raw3 = ((const float2*)(xin + (size_t)c3.x * 64))[lane];
                float a0 = __int_as_float(c0.y), a1 = __int_as_float(c1.y);
                float a2 = __int_as_float(c2.y), a3 = __int_as_float(c3.y);
                float2 p;
                p = __half22float2(*(const __half2*)&raw0.x);
                acc.x = fmaf(a0, p.x, acc.x); acc.y = fmaf(a0, p.y, acc.y);
                p = __half22float2(*(const __half2*)&raw0.y);
                acc.z = fmaf(a0, p.x, acc.z); acc.w = fmaf(a0, p.y, acc.w);
                p = __half22float2(*(const __half2*)&raw1.x);
                acc.x = fmaf(a1, p.x, acc.x); acc.y = fmaf(a1, p.y, acc.y);
                p = __half22float2(*(const __half2*)&raw1.y);
                acc.z = fmaf(a1, p.x, acc.z); acc.w = fmaf(a1, p.y, acc.w);
                p = __half22float2(*(const __half2*)&raw2.x);
                acc.x = fmaf(a2, p.x, acc.x); acc.y = fmaf(a2, p.y, acc.y);
                p = __half22float2(*(const __half2*)&raw2.y);
                acc.z = fmaf(a2, p.x, acc.z); acc.w = fmaf(a2, p.y, acc.w);
                p = __half22float2(*(const __half2*)&raw3.x);
                acc.x = fmaf(a3, p.x, acc.x); acc.y = fmaf(a3, p.y, acc.y);
                p = __half22float2(*(const __half2*)&raw3.y);
                acc.z = fmaf(a3, p.x, acc.z); acc.w = fmaf(a3, p.y, acc.w);
                e = en;
                if (!more) break;
                c0 = n0; c1 = n1; c2 = n2; c3 = n3;
            }
        }
        for (; e < end; e++) {
            int2 er = g_edge[e];
            float2 raw = ((const float2*)(xin + (size_t)er.x * 64))[lane];
            float a = __int_as_float(er.y);
            float2 p0 = __half22float2(*(const __half2*)&raw.x);
            float2 p1 = __half22float2(*(const __half2*)&raw.y);
            acc.x = fmaf(a, p0.x, acc.x); acc.y = fmaf(a, p0.y, acc.y);
            acc.z = fmaf(a, p1.x, acc.z); acc.w = fmaf(a, p1.y, acc.w);
        }
        *(float4*)(&g_hn[(size_t)gw * 128 + lane * 4]) = acc;
    } else {
        float2 acc = make_float2(0.f, 0.f);
        int e = beg;
        if (e + 3 < end) {
            int2 c0 = g_edge[e], c1 = g_edge[e + 1], c2 = g_edge[e + 2], c3 = g_edge[e + 3];
            for (;;) {
                int en = e + 4;
                bool more = (en + 3 < end);
                int2 n0, n1, n2, n3;
                if (more) { n0 = g_edge[en]; n1 = g_edge[en + 1]; n2 = g_edge[en + 2]; n3 = g_edge[en + 3]; }
                __half2 h0 = xin[(size_t)c0.x * 32 + lane];
                __half2 h1 = xin[(size_t)c1.x * 32 + lane];
                __half2 h2 = xin[(size_t)c2.x * 32 + lane];
                __half2 h3 = xin[(size_t)c3.x * 32 + lane];
                float2 p;
                p = __half22float2(h0); float a0 = __int_as_float(c0.y);
                acc.x = fmaf(a0, p.x, acc.x); acc.y = fmaf(a0, p.y, acc.y);
                p = __half22float2(h1); float a1 = __int_as_float(c1.y);
                acc.x = fmaf(a1, p.x, acc.x); acc.y = fmaf(a1, p.y, acc.y);
                p = __half22float2(h2); float a2 = __int_as_float(c2.y);
                acc.x = fmaf(a2, p.x, acc.x); acc.y = fmaf(a2, p.y, acc.y);
                p = __half22float2(h3); float a3 = __int_as_float(c3.y);
                acc.x = fmaf(a3, p.x, acc.x); acc.y = fmaf(a3, p.y, acc.y);
                e = en;
                if (!more) break;
                c0 = n0; c1 = n1; c2 = n2; c3 = n3;
            }
        }
        for (; e < end; e++) {
            int2 er = g_edge[e];
            __half2 h = xin[(size_t)er.x * 32 + lane];
            float a = __int_as_float(er.y);
            float2 p = __half22float2(h);
            acc.x = fmaf(a, p.x, acc.x); acc.y = fmaf(a, p.y, acc.y);
        }
        *(float2*)(&g_hn[(size_t)gw * 64 + lane * 2]) = acc;
    }
}

// ---------------- fused bi-interaction via wmma (HMMA) ----------------
// Block tile BM=64 nodes x BN cols, NTH threads. Warp layout: WN col-groups x WM row-groups.
template <int IN, int OUT, int BN, int NTH>
__global__ void __launch_bounds__(NTH)
k_fuse_mma(const float* __restrict__ xin, int xstride,
           const half* __restrict__ W1h, const float* __restrict__ b1,
           const half* __restrict__ W2h, const float* __restrict__ b2,
           float* __restrict__ out, int outcol, __half2* __restrict__ hh) {
    constexpr int BM = 64;
    constexpr int WN = (BN >= 64) ? BN / 64 : 1;   // warp col groups
    constexpr int CW = BN / WN;                     // cols per warp
    constexpr int NF = CW / 16;
    constexpr int WM = (NTH / 32) / WN;             // warp row groups
    constexpr int RW = BM / WM;                     // rows per warp (=16)
    static_assert(RW == 16, "row tile must be 16");

    extern __shared__ __align__(16) char sm[];
    half*  s_s = (half*)sm;                    // [BM][IN]
    half*  s_p = s_s + (size_t)BM * IN;        // [BM][IN]
    float* o1  = (float*)sm;                   // [BM][BN] (aliases operands after sync)
    float* o2  = o1 + (size_t)BM * BN;

    int tid = threadIdx.x;
    int wid = tid >> 5;
    int v0 = blockIdx.x * BM;
    int j0 = blockIdx.y * BN;

    // build S = x+h, P = x*h (fp16)
    for (int i = tid; i < BM * (IN / 2); i += NTH) {
        int n = i / (IN / 2), k2 = i % (IN / 2);
        int v = v0 + n;
        float2 xv = make_float2(0.f, 0.f), hv = make_float2(0.f, 0.f);
        if (v < NN) {
            xv = *(const float2*)&xin[(size_t)v * xstride + k2 * 2];
            hv = *(const float2*)&g_hn[(size_t)v * IN + k2 * 2];
        }
        *(__half2*)&s_s[(size_t)n * IN + k2 * 2] = __floats2half2_rn(xv.x + hv.x, xv.y + hv.y);
        *(__half2*)&s_p[(size_t)n * IN + k2 * 2] = __floats2half2_rn(xv.x * hv.x, xv.y * hv.y);
    }
    __syncthreads();

    int wn = wid % WN;
    int wm = wid / WN;
    int r0 = wm * 16;
    int c0 = wn * CW;

    wmma::fragment<wmma::accumulator, 16, 16, 16, float> acc1[NF], acc2[NF];
    #pragma unroll
    for (int ni = 0; ni < NF; ni++) {
        wmma::fill_fragment(acc1[ni], 0.f);
        wmma::fill_fragment(acc2[ni], 0.f);
    }

    for (int kc = 0; kc < IN; kc += 16) {
        wmma::fragment<wmma::matrix_a, 16, 16, 16, half, wmma::row_major> a1, a2;
        wmma::load_matrix_sync(a1, &s_s[(size_t)r0 * IN + kc], IN);
        wmma::load_matrix_sync(a2, &s_p[(size_t)r0 * IN + kc], IN);
        #pragma unroll
        for (int ni = 0; ni < NF; ni++) {
            int j = j0 + c0 + ni * 16;
            wmma::fragment<wmma::matrix_b, 16, 16, 16, half, wmma::row_major> bf1, bf2;
            wmma::load_matrix_sync(bf1, &W1h[(size_t)kc * OUT + j], OUT);
            wmma::load_matrix_sync(bf2, &W2h[(size_t)kc * OUT + j], OUT);
            wmma::mma_sync(acc1[ni], a1, bf1, acc1[ni]);
            wmma::mma_sync(acc2[ni], a2, bf2, acc2[ni]);
        }
    }

    __syncthreads();  // operand tiles dead; reuse as epilogue buffers
    #pragma unroll
    for (int ni = 0; ni < NF; ni++) {
        wmma::store_matrix_sync(&o1[(size_t)r0 * BN + c0 + ni * 16], acc1[ni], BN, wmma::mem_row_major);
        wmma::store_matrix_sync(&o2[(size_t)r0 * BN + c0 + ni * 16], acc2[ni], BN, wmma::mem_row_major);
    }
    __syncthreads();

    for (int i = tid; i < BM * (BN / 2); i += NTH) {
        int n = i / (BN / 2), j2 = i % (BN / 2);
        int v = v0 + n;
        if (v < NN) {
            int j = j2 * 2;
            float r1a = o1[(size_t)n * BN + j]     + b1[j0 + j];
            float r1b = o1[(size_t)n * BN + j + 1] + b1[j0 + j + 1];
            float r2a = o2[(size_t)n * BN + j]     + b2[j0 + j];
            float r2b = o2[(size_t)n * BN + j + 1] + b2[j0 + j + 1];
            r1a = r1a > 0.f ? r1a : 0.01f * r1a;
            r1b = r1b > 0.f ? r1b : 0.01f * r1b;
            r2a = r2a > 0.f ? r2a : 0.01f * r2a;
            r2b = r2b > 0.f ? r2b : 0.01f * r2b;
            float ra = r1a + r2a, rb = r1b + r2b;
            *(float2*)&out[(size_t)v * 352 + outcol + j0 + j] = make_float2(ra, rb);
            if (hh) hh[(size_t)v * (OUT / 2) + ((j0 + j) >> 1)] = __floats2half2_rn(ra, rb);
        }
    }
}

// ---------------- launch ----------------
extern "C" void kernel_launch(void* const* d_in, const int* in_sizes, int n_in,
                              void* d_out, int out_size) {
    const float* x    = (const float*)d_in[0];
    const int*   src  = (const int*)d_in[1];
    const int*   dst  = (const int*)d_in[2];
    const float* attn = (const float*)d_in[3];
    const float* W1_0 = (const float*)d_in[4];
    const float* b1_0 = (const float*)d_in[5];
    const float* W2_0 = (const float*)d_in[6];
    const float* b2_0 = (const float*)d_in[7];
    const float* W1_1 = (const float*)d_in[8];
    const float* b1_1 = (const float*)d_in[9];
    const float* W2_1 = (const float*)d_in[10];
    const float* b2_1 = (const float*)d_in[11];
    const float* W1_2 = (const float*)d_in[12];
    const float* b1_2 = (const float*)d_in[13];
    const float* W2_2 = (const float*)d_in[14];
    const float* b2_2 = (const float*)d_in[15];
    float* out = (float*)d_out;

    __half2 *xh, *hh;
    half *wpool;
    cudaGetSymbolAddress((void**)&xh, g_xh);
    cudaGetSymbolAddress((void**)&hh, g_hh);
    cudaGetSymbolAddress((void**)&wpool, g_wpool);
    const int N0 = 128 * 128, N1 = 128 * 64, N2 = 64 * 32;
    half* w1_0 = wpool;
    half* w2_0 = w1_0 + N0;
    half* w1_1 = w2_0 + N0;
    half* w2_1 = w1_1 + N1;
    half* w1_2 = w2_1 + N1;
    half* w2_2 = w1_2 + N2;

    // opt-in dynamic smem for layer-0 fuse (64KB)
    cudaFuncSetAttribute((const void*)k_fuse_mma<128, 128, 128, 256>,
                         cudaFuncAttributeMaxDynamicSharedMemorySize, 65536);

    // CSR build
    k_zero_deg<<<(NN + 255) / 256, 256>>>();
    k_hist<<<(NE / 4 + 255) / 256, 256>>>(dst);
    k_scan<<<1, 1024>>>();
    k_scatter<<<(NE / 4 + 255) / 256, 256>>>(src, dst, attn);

    // fp16 weights (one kernel)
    k_convw_all<<<(2 * (N0 + N1 + N2) + 255) / 256, 256>>>(W1_0, W2_0, W1_1, W2_1, W1_2, W2_2);

    // output cols [0,128) = x ; fp16 mirror of x
    k_copy_x<<<(NN * 32 + 255) / 256, 256>>>(x, out);

    const int aggBlocks = (NN * 32 + 255) / 256;
    const int fuseGrid = (NN + 63) / 64;

    // layer 0: IN=128 -> OUT=128, one block covers all 128 cols
    k_agg<4><<<aggBlocks, 256>>>(xh);
    k_fuse_mma<128, 128, 128, 256><<<fuseGrid, 256, 65536>>>(x, 128, w1_0, b1_0, w2_0, b2_0, out, 128, hh);

    // layer 1: IN=128 -> OUT=64
    k_agg<4><<<aggBlocks, 256>>>(hh);
    k_fuse_mma<128, 64, 64, 128><<<fuseGrid, 128, 32768>>>(out + 128, 352, w1_1, b1_1, w2_1, b2_1, out, 256, hh);

    // layer 2: IN=64 -> OUT=32
    k_agg<2><<<aggBlocks, 256>>>(hh);
    k_fuse_mma<64, 32, 32, 128><<<fuseGrid, 128, 16384>>>(out + 256, 352, w1_2, b1_2, w2_2, b2_2, out, 320, nullptr);
}

// round 5
// speedup vs baseline: 1.1433x; 1.1433x over previous
#include <cuda_runtime.h>
#include <cuda_fp16.h>
#include <mma.h>
#include <cstdint>

using namespace nvcuda;

#define NN 100000
#define NE 3200000

// ---------------- static device scratch (no allocations allowed) ----------------
__device__ int     g_deg[NN];
__device__ int     g_off[NN + 1];
__device__ int     g_cursor[NN];
__device__ int2    g_edge[NE];             // (src, bitcast(attn)) sorted by dst
__device__ float   g_hn[(size_t)NN * 128]; // aggregation result (fp32), stride = IN
__device__ __half2 g_xh[(size_t)NN * 64];  // fp16 mirror of x (128 cols)
__device__ __half2 g_hh[(size_t)NN * 64];  // fp16 mirror of current layer output
// fp16 weights
__device__ half g_w1_0[128 * 128];
__device__ half g_w2_0[128 * 128];
__device__ half g_w1_1[128 * 64];
__device__ half g_w2_1[128 * 64];
__device__ half g_w1_2[64 * 32];
__device__ half g_w2_2[64 * 32];

// ---------------- CSR build ----------------
__global__ void k_zero_deg() {
    int i = blockIdx.x * blockDim.x + threadIdx.x;
    if (i < NN) g_deg[i] = 0;
}

__global__ void k_hist(const int* __restrict__ dst) {
    int base = (blockIdx.x * blockDim.x + threadIdx.x) * 4;
    if (base + 3 < NE) {
        int4 d = *(const int4*)&dst[base];
        atomicAdd(&g_deg[d.x], 1);
        atomicAdd(&g_deg[d.y], 1);
        atomicAdd(&g_deg[d.z], 1);
        atomicAdd(&g_deg[d.w], 1);
    } else {
        for (int e = base; e < NE; e++) atomicAdd(&g_deg[dst[e]], 1);
    }
}

// single-block scan: each thread serially owns a contiguous chunk
__global__ void k_scan() {
    __shared__ int part[1024];
    int tid = threadIdx.x;
    const int CH = (NN + 1023) / 1024;
    int beg = tid * CH;
    int end = beg + CH < NN ? beg + CH : NN;
    int s = 0;
    for (int i = beg; i < end; i++) s += g_deg[i];
    part[tid] = s;
    __syncthreads();
    #pragma unroll
    for (int off = 1; off < 1024; off <<= 1) {
        int t = (tid >= off) ? part[tid - off] : 0;
        __syncthreads();
        part[tid] += t;
        __syncthreads();
    }
    int run = tid ? part[tid - 1] : 0;
    for (int i = beg; i < end; i++) {
        int d = g_deg[i];
        g_off[i] = run;
        g_cursor[i] = run;
        run += d;
    }
    if (tid == 1023) g_off[NN] = run;
}

__global__ void k_scatter(const int* __restrict__ src, const int* __restrict__ dst,
                          const float* __restrict__ attn) {
    int base = (blockIdx.x * blockDim.x + threadIdx.x) * 4;
    if (base + 3 < NE) {
        int4   s = *(const int4*)&src[base];
        int4   d = *(const int4*)&dst[base];
        float4 a = *(const float4*)&attn[base];
        int p0 = atomicAdd(&g_cursor[d.x], 1);
        int p1 = atomicAdd(&g_cursor[d.y], 1);
        int p2 = atomicAdd(&g_cursor[d.z], 1);
        int p3 = atomicAdd(&g_cursor[d.w], 1);
        g_edge[p0] = make_int2(s.x, __float_as_int(a.x));
        g_edge[p1] = make_int2(s.y, __float_as_int(a.y));
        g_edge[p2] = make_int2(s.z, __float_as_int(a.z));
        g_edge[p3] = make_int2(s.w, __float_as_int(a.w));
    } else {
        for (int e = base; e < NE; e++) {
            int p = atomicAdd(&g_cursor[dst[e]], 1);
            g_edge[p] = make_int2(src[e], __float_as_int(attn[e]));
        }
    }
}

// ---------------- weight fp32 -> fp16 ----------------
__global__ void k_convw(const float* __restrict__ W, half* __restrict__ Wh, int n) {
    int i = blockIdx.x * blockDim.x + threadIdx.x;
    if (i < n) Wh[i] = __float2half(W[i]);
}

// ---------------- copy x into output cols [0,128) + fp16 mirror ----------------
__global__ void k_copy_x(const float* __restrict__ x, float* __restrict__ out) {
    int t = blockIdx.x * blockDim.x + threadIdx.x;
    if (t < NN * 32) {
        int v = t >> 5, c = t & 31;
        float4 val = ((const float4*)(x + (size_t)v * 128))[c];
        ((float4*)(out + (size_t)v * 352))[c] = val;
        g_xh[(size_t)v * 64 + c * 2]     = __floats2half2_rn(val.x, val.y);
        g_xh[(size_t)v * 64 + c * 2 + 1] = __floats2half2_rn(val.z, val.w);
    }
}

// ---------------- aggregation, D=128: TWO warps per node (64 cols each) ----------------
// lane reads one __half2 (4B); warp covers 128B contiguous of the row. 8-edge unroll.
__global__ void k_agg_half(const __half2* __restrict__ xin) {
    int gw = (blockIdx.x * blockDim.x + threadIdx.x) >> 5;
    if (gw >= NN * 2) return;
    int node = gw >> 1;
    int halfsel = gw & 1;
    int lane = threadIdx.x & 31;
    const __half2* base = xin + halfsel * 32 + lane;
    int beg = g_off[node], end = g_off[node + 1];

    float2 acc = make_float2(0.f, 0.f);
    int e = beg;
    for (; e + 7 < end; e += 8) {
        int2 er[8];
        #pragma unroll
        for (int i = 0; i < 8; i++) er[i] = g_edge[e + i];
        __half2 h[8];
        #pragma unroll
        for (int i = 0; i < 8; i++) h[i] = base[(size_t)er[i].x * 64];
        #pragma unroll
        for (int i = 0; i < 8; i++) {
            float a = __int_as_float(er[i].y);
            float2 p = __half22float2(h[i]);
            acc.x = fmaf(a, p.x, acc.x);
            acc.y = fmaf(a, p.y, acc.y);
        }
    }
    for (; e < end; e++) {
        int2 er = g_edge[e];
        __half2 h = base[(size_t)er.x * 64];
        float a = __int_as_float(er.y);
        float2 p = __half22float2(h);
        acc.x = fmaf(a, p.x, acc.x);
        acc.y = fmaf(a, p.y, acc.y);
    }
    *(float2*)&g_hn[(size_t)node * 128 + halfsel * 64 + lane * 2] = acc;
}

// ---------------- aggregation, D=64: warp per node, 8-edge unroll ----------------
__global__ void k_agg64(const __half2* __restrict__ xin) {
    int gw = (blockIdx.x * blockDim.x + threadIdx.x) >> 5;
    if (gw >= NN) return;
    int lane = threadIdx.x & 31;
    const __half2* base = xin + lane;
    int beg = g_off[gw], end = g_off[gw + 1];

    float2 acc = make_float2(0.f, 0.f);
    int e = beg;
    for (; e + 7 < end; e += 8) {
        int2 er[8];
        #pragma unroll
        for (int i = 0; i < 8; i++) er[i] = g_edge[e + i];
        __half2 h[8];
        #pragma unroll
        for (int i = 0; i < 8; i++) h[i] = base[(size_t)er[i].x * 32];
        #pragma unroll
        for (int i = 0; i < 8; i++) {
            float a = __int_as_float(er[i].y);
            float2 p = __half22float2(h[i]);
            acc.x = fmaf(a, p.x, acc.x);
            acc.y = fmaf(a, p.y, acc.y);
        }
    }
    for (; e < end; e++) {
        int2 er = g_edge[e];
        __half2 h = base[(size_t)er.x * 32];
        float a = __int_as_float(er.y);
        float2 p = __half22float2(h);
        acc.x = fmaf(a, p.x, acc.x);
        acc.y = fmaf(a, p.y, acc.y);
    }
    *(float2*)&g_hn[(size_t)gw * 64 + lane * 2] = acc;
}

// ---------------- fused bi-interaction via wmma (HMMA) — round-3 config ----------------
// 128 threads = 4 warps; block tile BM=64 nodes x BN cols; warp tile 32 x BN/2.
template <int IN, int OUT, int BN>
__global__ void __launch_bounds__(128)
k_fuse_mma(const float* __restrict__ xin, int xstride,
           const half* __restrict__ W1h, const float* __restrict__ b1,
           const half* __restrict__ W2h, const float* __restrict__ b2,
           float* __restrict__ out, int outcol, __half2* __restrict__ hh) {
    constexpr int BM = 64;
    constexpr int NF = BN / 32;                // 16-wide n-frags per warp
    constexpr size_t OPER_BYTES = (size_t)2 * BM * IN * sizeof(half);
    constexpr size_t EPI_BYTES  = (size_t)2 * BM * BN * sizeof(float);
    constexpr size_t SBYTES = OPER_BYTES > EPI_BYTES ? OPER_BYTES : EPI_BYTES;
    __shared__ __align__(16) char sm[SBYTES];
    half*  s_s = (half*)sm;                    // [BM][IN]
    half*  s_p = s_s + (size_t)BM * IN;        // [BM][IN]
    float* o1  = (float*)sm;                   // [BM][BN] (aliases s_s/s_p after sync)
    float* o2  = o1 + (size_t)BM * BN;

    int tid = threadIdx.x;
    int wid = tid >> 5;
    int v0 = blockIdx.x * BM;
    int j0 = blockIdx.y * BN;

    // build S = x+h, P = x*h (fp16)
    for (int i = tid; i < BM * (IN / 2); i += 128) {
        int n = i / (IN / 2), k2 = i % (IN / 2);
        int v = v0 + n;
        float2 xv = make_float2(0.f, 0.f), hv = make_float2(0.f, 0.f);
        if (v < NN) {
            xv = *(const float2*)&xin[(size_t)v * xstride + k2 * 2];
            hv = *(const float2*)&g_hn[(size_t)v * IN + k2 * 2];
        }
        *(__half2*)&s_s[(size_t)n * IN + k2 * 2] = __floats2half2_rn(xv.x + hv.x, xv.y + hv.y);
        *(__half2*)&s_p[(size_t)n * IN + k2 * 2] = __floats2half2_rn(xv.x * hv.x, xv.y * hv.y);
    }
    __syncthreads();

    int wm = wid >> 1;  // 0..1 : row group
    int wn = wid & 1;   // 0..1 : col group

    wmma::fragment<wmma::accumulator, 16, 16, 16, float> acc1[2][NF], acc2[2][NF];
    #pragma unroll
    for (int mi = 0; mi < 2; mi++)
        #pragma unroll
        for (int ni = 0; ni < NF; ni++) {
            wmma::fill_fragment(acc1[mi][ni], 0.f);
            wmma::fill_fragment(acc2[mi][ni], 0.f);
        }

    for (int kc = 0; kc < IN; kc += 16) {
        wmma::fragment<wmma::matrix_a, 16, 16, 16, half, wmma::row_major> a1[2], a2[2];
        #pragma unroll
        for (int mi = 0; mi < 2; mi++) {
            wmma::load_matrix_sync(a1[mi], &s_s[(size_t)(wm * 32 + mi * 16) * IN + kc], IN);
            wmma::load_matrix_sync(a2[mi], &s_p[(size_t)(wm * 32 + mi * 16) * IN + kc], IN);
        }
        #pragma unroll
        for (int ni = 0; ni < NF; ni++) {
            int j = j0 + wn * (BN / 2) + ni * 16;
            wmma::fragment<wmma::matrix_b, 16, 16, 16, half, wmma::row_major> bf1, bf2;
            wmma::load_matrix_sync(bf1, &W1h[(size_t)kc * OUT + j], OUT);
            wmma::load_matrix_sync(bf2, &W2h[(size_t)kc * OUT + j], OUT);
            #pragma unroll
            for (int mi = 0; mi < 2; mi++) {
                wmma::mma_sync(acc1[mi][ni], a1[mi], bf1, acc1[mi][ni]);
                wmma::mma_sync(acc2[mi][ni], a2[mi], bf2, acc2[mi][ni]);
            }
        }
    }

    __syncthreads();  // operand tiles dead; reuse as epilogue buffers
    #pragma unroll
    for (int mi = 0; mi < 2; mi++)
        #pragma unroll
        for (int ni = 0; ni < NF; ni++) {
            int r = wm * 32 + mi * 16;
            int c = wn * (BN / 2) + ni * 16;
            wmma::store_matrix_sync(&o1[(size_t)r * BN + c], acc1[mi][ni], BN, wmma::mem_row_major);
            wmma::store_matrix_sync(&o2[(size_t)r * BN + c], acc2[mi][ni], BN, wmma::mem_row_major);
        }
    __syncthreads();

    for (int i = tid; i < BM * (BN / 2); i += 128) {
        int n = i / (BN / 2), j2 = i % (BN / 2);
        int v = v0 + n;
        if (v < NN) {
            int j = j2 * 2;
            float r1a = o1[(size_t)n * BN + j]     + b1[j0 + j];
            float r1b = o1[(size_t)n * BN + j + 1] + b1[j0 + j + 1];
            float r2a = o2[(size_t)n * BN + j]     + b2[j0 + j];
            float r2b = o2[(size_t)n * BN + j + 1] + b2[j0 + j + 1];
            r1a = r1a > 0.f ? r1a : 0.01f * r1a;
            r1b = r1b > 0.f ? r1b : 0.01f * r1b;
            r2a = r2a > 0.f ? r2a : 0.01f * r2a;
            r2b = r2b > 0.f ? r2b : 0.01f * r2b;
            float ra = r1a + r2a, rb = r1b + r2b;
            *(float2*)&out[(size_t)v * 352 + outcol + j0 + j] = make_float2(ra, rb);
            if (hh) hh[(size_t)v * (OUT / 2) + ((j0 + j) >> 1)] = __floats2half2_rn(ra, rb);
        }
    }
}

// ---------------- launch ----------------
extern "C" void kernel_launch(void* const* d_in, const int* in_sizes, int n_in,
                              void* d_out, int out_size) {
    const float* x    = (const float*)d_in[0];
    const int*   src  = (const int*)d_in[1];
    const int*   dst  = (const int*)d_in[2];
    const float* attn = (const float*)d_in[3];
    const float* W1_0 = (const float*)d_in[4];
    const float* b1_0 = (const float*)d_in[5];
    const float* W2_0 = (const float*)d_in[6];
    const float* b2_0 = (const float*)d_in[7];
    const float* W1_1 = (const float*)d_in[8];
    const float* b1_1 = (const float*)d_in[9];
    const float* W2_1 = (const float*)d_in[10];
    const float* b2_1 = (const float*)d_in[11];
    const float* W1_2 = (const float*)d_in[12];
    const float* b1_2 = (const float*)d_in[13];
    const float* W2_2 = (const float*)d_in[14];
    const float* b2_2 = (const float*)d_in[15];
    float* out = (float*)d_out;

    __half2 *xh, *hh;
    half *w1_0, *w2_0, *w1_1, *w2_1, *w1_2, *w2_2;
    cudaGetSymbolAddress((void**)&xh, g_xh);
    cudaGetSymbolAddress((void**)&hh, g_hh);
    cudaGetSymbolAddress((void**)&w1_0, g_w1_0);
    cudaGetSymbolAddress((void**)&w2_0, g_w2_0);
    cudaGetSymbolAddress((void**)&w1_1, g_w1_1);
    cudaGetSymbolAddress((void**)&w2_1, g_w2_1);
    cudaGetSymbolAddress((void**)&w1_2, g_w1_2);
    cudaGetSymbolAddress((void**)&w2_2, g_w2_2);

    // CSR build
    k_zero_deg<<<(NN + 255) / 256, 256>>>();
    k_hist<<<(NE / 4 + 255) / 256, 256>>>(dst);
    k_scan<<<1, 1024>>>();
    k_scatter<<<(NE / 4 + 255) / 256, 256>>>(src, dst, attn);

    // fp16 weights
    k_convw<<<(128 * 128 + 255) / 256, 256>>>(W1_0, w1_0, 128 * 128);
    k_convw<<<(128 * 128 + 255) / 256, 256>>>(W2_0, w2_0, 128 * 128);
    k_convw<<<(128 * 64 + 255) / 256, 256>>>(W1_1, w1_1, 128 * 64);
    k_convw<<<(128 * 64 + 255) / 256, 256>>>(W2_1, w2_1, 128 * 64);
    k_convw<<<(64 * 32 + 255) / 256, 256>>>(W1_2, w1_2, 64 * 32);
    k_convw<<<(64 * 32 + 255) / 256, 256>>>(W2_2, w2_2, 64 * 32);

    // output cols [0,128) = x ; fp16 mirror of x
    k_copy_x<<<(NN * 32 + 255) / 256, 256>>>(x, out);

    const int aggHalfBlocks = (NN * 2 * 32 + 255) / 256;
    const int agg64Blocks = (NN * 32 + 255) / 256;
    const int fuseGrid = (NN + 63) / 64;

    // layer 0: IN=128 -> OUT=128
    k_agg_half<<<aggHalfBlocks, 256>>>(xh);
    {
        dim3 g(fuseGrid, 2);
        k_fuse_mma<128, 128, 64><<<g, 128>>>(x, 128, w1_0, b1_0, w2_0, b2_0, out, 128, hh);
    }
    // layer 1: IN=128 -> OUT=64
    k_agg_half<<<aggHalfBlocks, 256>>>(hh);
    {
        dim3 g(fuseGrid, 1);
        k_fuse_mma<128, 64, 64><<<g, 128>>>(out + 128, 352, w1_1, b1_1, w2_1, b2_1, out, 256, hh);
    }
    // layer 2: IN=64 -> OUT=32
    k_agg64<<<agg64Blocks, 256>>>(hh);
    {
        dim3 g(fuseGrid, 1);
        k_fuse_mma<64, 32, 32><<<g, 128>>>(out + 256, 352, w1_2, b1_2, w2_2, b2_2, out, 320, nullptr);
    }
}